// round 7
// baseline (speedup 1.0000x reference)
#include <cuda_runtime.h>
#include <cuda_bf16.h>
#include <math.h>

#define L_TOT 5456
#define NB    32
#define FIN   32
#define FOUT  64
#define BATCH 4
#define NGRID 12
#define ZI    128   // BATCH*FIN
#define ZO    256   // BATCH*FOUT

typedef unsigned long long ull;

// -------- scratch (device globals; no runtime allocation) --------
// Xf layout: [b*1024 + mi*32 + ni][zi]  (zi innermost -> coalesced in K2)
__device__ float2 g_Xf[(size_t)NB * 1024 * ZI];                    // 33.5 MB
__device__ float2 g_xh[(size_t)L_TOT * ZI];                        // 5.6 MB
__device__ float2 g_yh[(size_t)L_TOT * FIN * FOUT];                // 89 MB (L2-resident)
__device__ float2 g_zh[(size_t)ZO * L_TOT];                        // 11.2 MB, layout [zo][lmn]

__device__ __forceinline__ int baseL(int l) {
    // sum_{l'<l} (2l'+1)^2 = l(2l-1)(2l+1)/3
    return l * (2 * l - 1) * (2 * l + 1) / 3;
}

// ---- packed f32x2 helpers (Blackwell FFMA2 path) ----
__device__ __forceinline__ ull pk2(unsigned lo, unsigned hi) {
    ull r;
    asm("mov.b64 %0, {%1, %2};" : "=l"(r) : "r"(lo), "r"(hi));
    return r;
}
__device__ __forceinline__ void fma2(ull& d, ull a, ull b) {
    asm("fma.rn.f32x2 %0, %1, %2, %0;" : "+l"(d) : "l"(a), "l"(b));
}

// ---- in-warp 32-point radix-2 DIF FFT via shuffles.
// Input: lane i holds x[i] (natural order). Output: lane i holds X[bitrev5(i)].
// Wt[k] must hold e^{sign*i*2*pi*k/32} (sign=-1 forward, +1 inverse).
__device__ __forceinline__ void warp_fft32(float& re, float& im, const float2* __restrict__ Wt) {
    int lane = threadIdx.x & 31;
    #pragma unroll
    for (int h = 16; h >= 1; h >>= 1) {
        float vr = __shfl_xor_sync(0xffffffffu, re, h);
        float vi = __shfl_xor_sync(0xffffffffu, im, h);
        int k = (lane & (h - 1)) * (16 / h);
        float2 w = Wt[k];
        if ((lane & h) == 0) {
            re += vr; im += vi;
        } else {
            float tr = vr - re, ti = vi - im;
            re = tr * w.x - ti * w.y;
            im = tr * w.y + ti * w.x;
        }
    }
}

__device__ __forceinline__ int brev5(int lane) { return (int)(__brev((unsigned)lane) >> 27); }

// ---------------- K1: forward FFT2 of x, writes transposed Xf ----------------
__global__ __launch_bounds__(1024) void k_fft_fwd(const float* __restrict__ x) {
    __shared__ float2 S[32][33];
    __shared__ float2 Wt[16];
    int plane = blockIdx.x;                 // = zi*32 + b
    int zi = plane >> 5, b = plane & 31;
    int tid = threadIdx.x;
    int w = tid >> 5, lane = tid & 31;
    if (tid < 16) {
        float s, c;
        sincosf(-6.283185307179586f * (float)tid / 32.0f, &s, &c);
        Wt[tid] = make_float2(c, s);
    }
    float re = x[(size_t)plane * 1024 + tid];   // row a=w, col g=lane
    float im = 0.f;
    __syncthreads();
    warp_fft32(re, im, Wt);
    S[w][brev5(lane)] = make_float2(re, im);
    __syncthreads();
    float2 v = S[lane][w];
    re = v.x; im = v.y;
    warp_fft32(re, im, Wt);
    int ma = brev5(lane);
    g_Xf[((size_t)(b * 1024 + ma * 32 + w)) * ZI + zi] = make_float2(re, im);
}

// ---------------- K2: xh[lmn][zi] = sum_b wf[b,lmn] * Xf[b,m&31,n&31][zi] ----------------
__global__ __launch_bounds__(128) void k_fwd_contract(const float* __restrict__ wf) {
    int lmn = blockIdx.x;
    int l = 0;
    while (l < 15 && lmn >= baseL(l + 1)) ++l;
    int n1 = 2 * l + 1;
    int rem = lmn - baseL(l);
    int m = rem / n1 - l, n = rem % n1 - l;
    int mi = m & 31, ni = n & 31;
    __shared__ float sw[32];
    int t = threadIdx.x;  // zi
    if (t < 32) sw[t] = __ldg(&wf[t * L_TOT + lmn]);
    __syncthreads();
    const float2* xp = g_Xf + ((size_t)(mi * 32 + ni)) * ZI + t;
    float2 acc = make_float2(0.f, 0.f);
    #pragma unroll 8
    for (int b = 0; b < 32; b++) {
        float w = sw[b];
        float2 v = xp[(size_t)b * 1024 * ZI];
        acc.x += w * v.x; acc.y += w * v.y;
    }
    g_xh[(size_t)lmn * ZI + t] = acc;
}

// ---------------- K3: yh[lmn][q] = sum_j D[lmn,j] * kernel[q,j]  (tiled) ----------------
#define K3_LT 64
__global__ __launch_bounds__(256) void k_kernel_ft(const float* __restrict__ D_re,
                                                   const float* __restrict__ D_im,
                                                   const float* __restrict__ kern) {
    __shared__ float2 sD[K3_LT][NGRID];
    __shared__ float  sk[256 * 13];
    int lmn0 = blockIdx.x * K3_LT;
    int q0   = blockIdx.y * 256;
    int tid  = threadIdx.x;
    for (int idx = tid; idx < K3_LT * NGRID; idx += 256) {
        int ll = idx / NGRID, j = idx % NGRID;
        int lmn = lmn0 + ll;
        float dr = 0.f, di = 0.f;
        if (lmn < L_TOT) { dr = D_re[lmn * NGRID + j]; di = D_im[lmn * NGRID + j]; }
        sD[ll][j] = make_float2(dr, di);
    }
    for (int idx = tid; idx < 256 * NGRID; idx += 256) {
        int qq = idx / NGRID, j = idx % NGRID;
        sk[qq * 13 + j] = kern[(size_t)(q0 + qq) * NGRID + j];
    }
    __syncthreads();
    float kreg[NGRID];
    #pragma unroll
    for (int j = 0; j < NGRID; j++) kreg[j] = sk[tid * 13 + j];
    int q = q0 + tid;
    #pragma unroll 4
    for (int ll = 0; ll < K3_LT; ll++) {
        int lmn = lmn0 + ll;
        if (lmn >= L_TOT) break;
        float2 acc = make_float2(0.f, 0.f);
        #pragma unroll
        for (int j = 0; j < NGRID; j++) {
            float2 d = sD[ll][j];
            acc.x += kreg[j] * d.x;
            acc.y += kreg[j] * d.y;
        }
        g_yh[(size_t)lmn * 2048 + q] = acc;
    }
}

// ---------------- K4: per-l block matmul  zh = x^l @ y^l  (FFMA2 path) ----------------
// tile = (l desc, m, chunk of 8 np). 256 threads = npp(8) x op(32).
// Each thread: 1 np, o-pair (2op, 2op+1), ALL 4 z in registers (packed f32x2 acc).
// x pre-duplicated in smem as (ax, ax, -ay, ay); y loaded once per (k,i) as LDG.128.
// tiles = sum_l (2l+1)*ceil((2l+1)/8) = 800
#define K4_GRID 800
#define K4_KC   16
__global__ __launch_bounds__(256) void k_so3mm() {
    int b = blockIdx.x;
    int l = 0, m = 0, ch = 0;
    {
        int off = 0;
        for (int ll = 15; ll >= 0; --ll) {
            int n1 = 2 * ll + 1, nch = (n1 + 7) >> 3;
            int cnt = n1 * nch;
            if (b < off + cnt) { l = ll; int r = b - off; m = r / nch; ch = r % nch; break; }
            off += cnt;
        }
    }
    int n1 = 2 * l + 1;
    int base = baseL(l);
    __shared__ uint4 sx[K4_KC][ZI];   // (ax, ax, -ay, ay) as bit patterns; 32 KB
    int tid = threadIdx.x;

    int op  = tid & 31;          // o pair: o = 2*op, 2*op+1
    int npp = tid >> 5;          // 0..7
    int np  = ch * 8 + npp;
    bool valid = np < n1;
    int npc = valid ? np : n1 - 1;

    ull acc[4][2];
    #pragma unroll
    for (int z = 0; z < 4; z++) { acc[z][0] = 0ull; acc[z][1] = 0ull; }

    for (int kc = 0; kc < n1; kc += K4_KC) {
        int kend = kc + K4_KC < n1 ? kc + K4_KC : n1;
        int cnt = (kend - kc) * ZI;
        __syncthreads();
        for (int idx = tid; idx < cnt; idx += 256) {
            int kk = idx >> 7, zi = idx & 127;
            float2 a = g_xh[(size_t)(base + m * n1 + kc + kk) * ZI + zi];
            float nay = -a.y;
            sx[kk][zi] = make_uint4(__float_as_uint(a.x), __float_as_uint(a.x),
                                    __float_as_uint(nay), __float_as_uint(a.y));
        }
        __syncthreads();

        for (int k = kc; k < kend; k++) {
            const uint4* row = reinterpret_cast<const uint4*>(
                g_yh + ((size_t)(base + k * n1 + npc)) * 2048);
            const uint4* xk = sx[k - kc];
            #pragma unroll 4
            for (int i = 0; i < FIN; i++) {
                uint4 y = __ldg(&row[i * 32 + op]);
                ull y01 = pk2(y.x, y.y);
                ull y10 = pk2(y.y, y.x);
                ull y23 = pk2(y.z, y.w);
                ull y32 = pk2(y.w, y.z);
                #pragma unroll
                for (int z = 0; z < 4; z++) {
                    uint4 xq = xk[z * FIN + i];
                    ull axax  = pk2(xq.x, xq.y);
                    ull nayay = pk2(xq.z, xq.w);
                    fma2(acc[z][0], axax,  y01);
                    fma2(acc[z][0], nayay, y10);
                    fma2(acc[z][1], axax,  y23);
                    fma2(acc[z][1], nayay, y32);
                }
            }
        }
    }
    if (valid) {
        int idx = base + m * n1 + np;
        int o0 = 2 * op;
        #pragma unroll
        for (int z = 0; z < 4; z++) {
            float2 r0 = make_float2(__uint_as_float((unsigned)(acc[z][0] & 0xffffffffull)),
                                    __uint_as_float((unsigned)(acc[z][0] >> 32)));
            float2 r1 = make_float2(__uint_as_float((unsigned)(acc[z][1] & 0xffffffffull)),
                                    __uint_as_float((unsigned)(acc[z][1] >> 32)));
            g_zh[(size_t)(z * 64 + o0)     * L_TOT + idx] = r0;
            g_zh[(size_t)(z * 64 + o0 + 1) * L_TOT + idx] = r1;
        }
    }
}

// ---------------- K5: fused scatter (wigner_inv * zh -> bins) + inverse FFT2 + real + bias ----------------
__global__ __launch_bounds__(1024) void k_inv(const float* __restrict__ wig,
                                              const float* __restrict__ bias,
                                              float* __restrict__ out) {
    __shared__ float2 P[32][33];
    __shared__ float  U[32][33];
    __shared__ float2 Wt[16];
    int blk = blockIdx.x;           // z*2048 + o*32 + b
    int bb = blk & 31;
    int o  = (blk >> 5) & 63;
    int z  = blk >> 11;
    int tid = threadIdx.x;
    int w = tid >> 5, lane = tid & 31;
    if (tid < 16) {
        float s, c;
        sincosf(6.283185307179586f * (float)tid / 32.0f, &s, &c);  // inverse: e^{+i...}
        Wt[tid] = make_float2(c, s);
    }
    P[w][lane] = make_float2(0.f, 0.f);
    __syncthreads();
    if (tid < 961) {
        int m = tid / 31 - 15, n = tid % 31 - 15;
        int am = m < 0 ? -m : m, an = n < 0 ? -n : n;
        int lmin = am > an ? am : an;
        float2 acc = make_float2(0.f, 0.f);
        const float2* zrow = g_zh + (size_t)(z * 64 + o) * L_TOT;
        const float*  wp   = wig + (size_t)bb * L_TOT;
        for (int l = lmin; l < 16; ++l) {
            int idx = baseL(l) + (m + l) * (2 * l + 1) + (n + l);
            float ww = __ldg(&wp[idx]);
            float2 v = zrow[idx];
            acc.x += ww * v.x; acc.y += ww * v.y;
        }
        P[m & 31][n & 31] = acc;
    }
    __syncthreads();
    {
        float2 v = P[w][lane];
        float re = v.x, im = v.y;
        warp_fft32(re, im, Wt);
        P[w][brev5(lane)] = make_float2(re, im);
    }
    __syncthreads();
    {
        float2 v = P[lane][w];
        float re = v.x, im = v.y;
        warp_fft32(re, im, Wt);
        U[brev5(lane)][w] = re * (1.0f / 1024.0f);   // real part only
    }
    __syncthreads();
    out[(size_t)blk * 1024 + tid] = U[w][lane] + __ldg(&bias[o]);
}

// ---------------- launch ----------------
extern "C" void kernel_launch(void* const* d_in, const int* in_sizes, int n_in,
                              void* d_out, int out_size) {
    const float* x    = (const float*)d_in[0];
    const float* kern = (const float*)d_in[1];
    const float* bias = (const float*)d_in[2];
    const float* wf   = (const float*)d_in[3];
    const float* wi   = (const float*)d_in[4];
    const float* D_re = (const float*)d_in[5];
    const float* D_im = (const float*)d_in[6];
    float* out = (float*)d_out;

    k_fft_fwd<<<BATCH * FIN * NB, 1024>>>(x);
    k_fwd_contract<<<L_TOT, ZI>>>(wf);
    k_kernel_ft<<<dim3((L_TOT + K3_LT - 1) / K3_LT, 8), 256>>>(D_re, D_im, kern);
    k_so3mm<<<K4_GRID, 256>>>();
    k_inv<<<BATCH * FOUT * NB, 1024>>>(wi, bias, out);
}